// round 10
// baseline (speedup 1.0000x reference)
#include <cuda_runtime.h>
#include <cuda_fp16.h>
#include <cstdint>
#include <math.h>

#define BB 8
#define SS 512
#define DD 256
#define NPAIRS (SS * (SS - 1) / 2)   // 130816
#define TILE 64
#define NTRI 36                      // lower-tri 64x64 tiles per batch

// ---- device globals (no cudaMalloc allowed) ----
__device__ float g_norms[BB * SS];
__device__ __align__(16) __half g_h[BB * SS * DD];   // fp16(x), 2MB

// tile index LUT: (ti<<4)|tj for t in [0,36)
__device__ const uint8_t c_tij[NTRI] = {
    0x00,
    0x10, 0x11,
    0x20, 0x21, 0x22,
    0x30, 0x31, 0x32, 0x33,
    0x40, 0x41, 0x42, 0x43, 0x44,
    0x50, 0x51, 0x52, 0x53, 0x54, 0x55,
    0x60, 0x61, 0x62, 0x63, 0x64, 0x65, 0x66,
    0x70, 0x71, 0x72, 0x73, 0x74, 0x75, 0x76, 0x77
};

// ---------------------------------------------------------------------------
__device__ __forceinline__ uint32_t smem_u32(const void* p) {
    uint32_t a;
    asm("{ .reg .u64 t; cvta.to.shared.u64 t, %1; cvt.u32.u64 %0, t; }" : "=r"(a) : "l"(p));
    return a;
}
__device__ __forceinline__ void cp_async16(uint32_t dst, const void* src) {
    asm volatile("cp.async.cg.shared.global [%0], [%1], 16;" :: "r"(dst), "l"(src) : "memory");
}
__device__ __forceinline__ void cp_commit() { asm volatile("cp.async.commit_group;" ::: "memory"); }
__device__ __forceinline__ void ldm_x4(uint32_t& r0, uint32_t& r1, uint32_t& r2, uint32_t& r3,
                                       uint32_t addr) {
    asm volatile("ldmatrix.sync.aligned.m8n8.x4.shared.b16 {%0,%1,%2,%3}, [%4];"
                 : "=r"(r0), "=r"(r1), "=r"(r2), "=r"(r3) : "r"(addr));
}
__device__ __forceinline__ void mma_f16(float* d, const uint32_t* a, const uint32_t* bfr) {
    asm volatile(
        "mma.sync.aligned.m16n8k16.row.col.f32.f16.f16.f32 "
        "{%0,%1,%2,%3}, {%4,%5,%6,%7}, {%8,%9}, {%0,%1,%2,%3};"
        : "+f"(d[0]), "+f"(d[1]), "+f"(d[2]), "+f"(d[3])
        : "r"(a[0]), "r"(a[1]), "r"(a[2]), "r"(a[3]), "r"(bfr[0]), "r"(bfr[1]));
}
__device__ __forceinline__ float sqrt_approx(float v) {
    float r;
    asm("sqrt.approx.f32 %0, %1;" : "=f"(r) : "f"(v));
    return r;
}

// ---------------------------------------------------------------------------
// Kernel 1: per-row norms (exact fp32) + fp16 conversion. One warp per row.
// ---------------------------------------------------------------------------
__global__ __launch_bounds__(256) void prep_kernel(const float* __restrict__ x) {
    int row = blockIdx.x * 8 + (threadIdx.x >> 5);
    int lane = threadIdx.x & 31;
    if (row >= BB * SS) return;
    const float4* x4 = reinterpret_cast<const float4*>(x) + (size_t)row * (DD / 4);
    float4 a = x4[lane];
    float4 c = x4[lane + 32];
    float s = a.x * a.x + a.y * a.y + a.z * a.z + a.w * a.w
            + c.x * c.x + c.y * c.y + c.z * c.z + c.w * c.w;
#pragma unroll
    for (int o = 16; o; o >>= 1) s += __shfl_xor_sync(0xFFFFFFFFu, s, o);
    if (lane == 0) g_norms[row] = s;

    size_t base = (size_t)row * DD;
#pragma unroll
    for (int g = 0; g < 2; ++g) {
        float4 v = g ? c : a;
        __half2 h0 = __floats2half2_rn(v.x, v.y);
        __half2 h1 = __floats2half2_rn(v.z, v.w);
        uint2 hv = make_uint2(*(uint32_t*)&h0, *(uint32_t*)&h1);
        *reinterpret_cast<uint2*>(g_h + base + g * 128 + lane * 4) = hv;
    }
}

// ---------------------------------------------------------------------------
// Kernel 2: 64x64 Gram tile per CTA, TWO warps (warp tile 64x32 -> 16 HMMA
// per 6 LDSM, 16 independent chains). Full-K tiles in smem (512B rows,
// XOR-16B swizzle), one cp.async group. fp32-accumulate mma.sync.
// DIAG template: B aliases A; fragments fully above the diagonal are
// compile-time skipped. sqrt.approx epilogue.
// smem: norms 512B + A 32KB + B 32KB = 64.5KB -> ~3 CTAs/SM by smem.
// ---------------------------------------------------------------------------
#define SM_NORM 512
#define SMEM_TOTAL (SM_NORM + 65536)

template <bool DIAG>
__device__ __forceinline__ void compute_tile(
    uint32_t abase, uint32_t bbase, const float* si, const float* sjn,
    int lane, int wn, int ti, int tj, float* __restrict__ ob) {

    int rA = lane & 15;
    int kselA = (lane >> 4) & 1;
    int rB = (lane & 7) | ((lane >> 1) & 8);
    int kselB = (lane >> 3) & 1;

    float acc[4][4][4];
#pragma unroll
    for (int mt = 0; mt < 4; ++mt)
#pragma unroll
        for (int nt = 0; nt < 4; ++nt)
#pragma unroll
            for (int e = 0; e < 4; ++e) acc[mt][nt][e] = 0.0f;

    uint32_t afr[2][4][4], bfr[2][2][4];
    auto load_frags = [&](int p, int ks) {
        uint32_t swA = ((ks * 2 + kselA) ^ (rA & 7)) * 16;
        uint32_t swB = ((ks * 2 + kselB) ^ (rB & 7)) * 16;
#pragma unroll
        for (int mt = 0; mt < 4; ++mt)
            ldm_x4(afr[p][mt][0], afr[p][mt][1], afr[p][mt][2], afr[p][mt][3],
                   abase + (mt * 16 + rA) * 512 + swA);
#pragma unroll
        for (int nh = 0; nh < 2; ++nh)
            ldm_x4(bfr[p][nh][0], bfr[p][nh][1], bfr[p][nh][2], bfr[p][nh][3],
                   bbase + (wn * 32 + nh * 16 + rB) * 512 + swB);
    };
    auto do_mma = [&](int p) {
#pragma unroll
        for (int mt = 0; mt < 4; ++mt)
#pragma unroll
            for (int nt = 0; nt < 4; ++nt) {
                int g = wn * 4 + nt;            // global 8-col block
                if (DIAG && g >= 2 * mt + 2) continue;  // frag entirely above diag
                uint32_t bb2[2] = { bfr[p][nt >> 1][(nt & 1) * 2],
                                    bfr[p][nt >> 1][(nt & 1) * 2 + 1] };
                mma_f16(acc[mt][nt], afr[p][mt], bb2);
            }
    };

    load_frags(0, 0);
#pragma unroll
    for (int ks = 0; ks < 16; ++ks) {
        if (ks < 15) load_frags((ks + 1) & 1, ks + 1);
        do_mma(ks & 1);
    }

    // epilogue
    int lr = lane >> 2;            // 0..7
    int lc = 2 * (lane & 3);       // 0,2,4,6
#pragma unroll
    for (int mt = 0; mt < 4; ++mt) {
        int r0 = mt * 16 + lr;
        int i0 = ti * TILE + r0;
        int i1 = i0 + 8;
        float n0 = si[r0], n1 = si[r0 + 8];
        int bs0 = i0 * (i0 - 1) / 2;
        int bs1 = i1 * (i1 - 1) / 2;
#pragma unroll
        for (int nt = 0; nt < 4; ++nt) {
            int g = wn * 4 + nt;
            if (DIAG && g >= 2 * mt + 2) continue;
            int col = g * 8 + lc;
            int j = tj * TILE + col;
            float njc0 = sjn[col], njc1 = sjn[col + 1];
            float* c = acc[mt][nt];
            if (j < i0)     ob[bs0 + j]     = sqrt_approx(fmaxf(n0 + njc0 - 2.0f * c[0], 1e-7f));
            if (j + 1 < i0) ob[bs0 + j + 1] = sqrt_approx(fmaxf(n0 + njc1 - 2.0f * c[1], 1e-7f));
            if (j < i1)     ob[bs1 + j]     = sqrt_approx(fmaxf(n1 + njc0 - 2.0f * c[2], 1e-7f));
            if (j + 1 < i1) ob[bs1 + j + 1] = sqrt_approx(fmaxf(n1 + njc1 - 2.0f * c[3], 1e-7f));
        }
    }
}

__global__ __launch_bounds__(64) void dist_kernel(float* __restrict__ out) {
    extern __shared__ char smem[];
    uint32_t sbase = smem_u32(smem);
    int tid = threadIdx.x;
    int lane = tid & 31;
    int wn = tid >> 5;   // warp -> 32-col half
    int b = blockIdx.y;

    uint32_t tij = c_tij[blockIdx.x];
    int ti = tij >> 4, tj = tij & 15;
    bool diag = (ti == tj);

    // norms: nrm[0..63]=si, [64..127]=sj
    float* nrm = reinterpret_cast<float*>(smem);
    nrm[tid] = g_norms[b * SS + ti * TILE + tid];
    nrm[64 + tid] = g_norms[b * SS + tj * TILE + tid];

    // full-K tile loads: warp covers one 512B row per iteration (coalesced)
    int kk = tid & 31, rh = tid >> 5;
    uint32_t abase = sbase + SM_NORM;
    uint32_t bbase = abase + 32768;
    {
        const __half* aSrc = g_h + ((size_t)(b * SS + ti * TILE)) * DD + kk * 8;
        const __half* bSrc = g_h + ((size_t)(b * SS + tj * TILE)) * DD + kk * 8;
#pragma unroll
        for (int q = 0; q < 32; ++q) {
            int r = rh + 2 * q;
            uint32_t sw = ((kk ^ (r & 7)) * 16);
            cp_async16(abase + r * 512 + sw, aSrc + (size_t)r * DD);
            if (!diag) cp_async16(bbase + r * 512 + sw, bSrc + (size_t)r * DD);
        }
        cp_commit();
    }
    asm volatile("cp.async.wait_group 0;" ::: "memory");
    __syncthreads();

    float* ob = out + (size_t)b * NPAIRS;
    if (diag)
        compute_tile<true>(abase, abase, nrm, nrm, lane, wn, ti, tj, ob);
    else
        compute_tile<false>(abase, bbase, nrm, nrm + 64, lane, wn, ti, tj, ob);
}

// ---------------------------------------------------------------------------
extern "C" void kernel_launch(void* const* d_in, const int* in_sizes, int n_in,
                              void* d_out, int out_size) {
    const float* x = (const float*)d_in[0];
    float* out = (float*)d_out;

    static bool attr_done = false;
    if (!attr_done) {
        cudaFuncSetAttribute(dist_kernel, cudaFuncAttributeMaxDynamicSharedMemorySize,
                             SMEM_TOTAL);
        attr_done = true;
    }

    prep_kernel<<<512, 256>>>(x);

    dim3 grid(NTRI, BB);
    dist_kernel<<<grid, 64, SMEM_TOTAL>>>(out);
}